// round 10
// baseline (speedup 1.0000x reference)
#include <cuda_runtime.h>
#include <cstdint>

// ============================================================================
// out[f32,4096x4096] = mat1[i32] @ mat2[i32] + input[i32], values in [0,16)
// Values fit u4 exactly -> mma.sync m16n8k64.u4 (8192 MAC/instr, 2x s8.k32).
// R10 (= R9 resubmit after container flake): nibble-packed operands, NKT=16,
// same SMEM geometry as the passing R8 kernel, 2 CTAs/SM.
// ============================================================================

#define MSZ 4096
#define KB2 (MSZ / 2)              // packed row bytes: 2048
#define BM 128
#define BN 128
#define BKV 256                    // k-values per kt (= 128 bytes packed)
#define BKB 128                    // bytes per kt
#define STAGES 3
#define NKT (MSZ / BKV)            // 16
#define ROWB 144                   // padded SMEM row: 128 data + 16 pad
#define STAGE_A (BM * ROWB)        // 18432
#define STAGE_B (BN * ROWB)        // 18432
#define STAGE_BYTES (STAGE_A + STAGE_B)      // 36864
#define SMEM_DYN (STAGES * STAGE_BYTES)      // 110592 -> 2 CTAs/SM

// Scratch (device globals; no allocation anywhere)
__device__ __align__(128) uint8_t g_packA[(size_t)MSZ * KB2];   // [M,K/2] u4-pairs
__device__ __align__(128) uint8_t g_packBt[(size_t)MSZ * KB2];  // [N,K/2] u4-pairs

// ---------------------------------------------------------------- helpers
__device__ __forceinline__ uint32_t smem_u32(const void* p) {
    uint32_t a;
    asm("{ .reg .u64 t; cvta.to.shared.u64 t, %1; cvt.u32.u64 %0, t; }"
        : "=r"(a) : "l"(p));
    return a;
}

#define CPA16(dst, src) \
    asm volatile("cp.async.cg.shared.global [%0], [%1], 16;" :: "r"(dst), "l"(src) : "memory")
#define CPC() asm volatile("cp.async.commit_group;" ::: "memory")
#define CPW(n) asm volatile("cp.async.wait_group %0;" :: "n"(n) : "memory")

#define LDSM4(r0, r1, r2, r3, addr) \
    asm volatile("ldmatrix.sync.aligned.m8n8.x4.shared.b16 {%0,%1,%2,%3}, [%4];" \
                 : "=r"(r0), "=r"(r1), "=r"(r2), "=r"(r3) : "r"(addr))

#define MMA_U4(d, a, b) \
    asm volatile("mma.sync.aligned.m16n8k64.row.col.s32.u4.u4.s32 " \
                 "{%0,%1,%2,%3}, {%4,%5,%6,%7}, {%8,%9}, {%0,%1,%2,%3};" \
                 : "+r"((d)[0]), "+r"((d)[1]), "+r"((d)[2]), "+r"((d)[3]) \
                 : "r"((a)[0]), "r"((a)[1]), "r"((a)[2]), "r"((a)[3]), \
                   "r"((b)[0]), "r"((b)[1]))

// stage loader: 128 threads; A 1024 + B 1024 16B chunks; 16 per thread.
#define LOAD_STAGE(kt, st) do {                                                           \
    const uint32_t sA_ = smbase + (st) * STAGE_BYTES;                                     \
    const uint32_t sB_ = sA_ + STAGE_A;                                                   \
    const uint8_t* pA_ = g_packA  + (size_t)m0 * KB2 + (size_t)(kt) * BKB;                \
    const uint8_t* pB_ = g_packBt + (size_t)n0 * KB2 + (size_t)(kt) * BKB;                \
    _Pragma("unroll")                                                                     \
    for (int i_ = 0; i_ < 8; i_++) {                                                      \
        const int row_ = ldRow + i_ * 16;                                                 \
        CPA16(sA_ + row_ * ROWB + ldSeg, pA_ + (size_t)row_ * KB2 + ldSeg);               \
        CPA16(sB_ + row_ * ROWB + ldSeg, pB_ + (size_t)row_ * KB2 + ldSeg);               \
    }                                                                                     \
    CPC();                                                                                \
} while (0)

// ---------------------------------------------------------------- fused pack
// blocks [0, 8192): packA -> nibbles. Each thread: 8 ints -> 4 bytes.
// blocks [8192, 12288): packBt tiles 128(k) x 32(n) -> nibble-transposed.
__global__ void pack_kernel(const int* __restrict__ A, const int* __restrict__ B) {
    if (blockIdx.x < 8192) {
        size_t i = (size_t)blockIdx.x * 256 + threadIdx.x;
        const int4* p = (const int4*)A + i * 2;
        int4 v0 = p[0], v1 = p[1];
        uchar4 r;
        r.x = (uint8_t)(v0.x | (v0.y << 4));
        r.y = (uint8_t)(v0.z | (v0.w << 4));
        r.z = (uint8_t)(v1.x | (v1.y << 4));
        r.w = (uint8_t)(v1.z | (v1.w << 4));
        ((uchar4*)g_packA)[i] = r;
    } else {
        __shared__ uint8_t tsm[32][132];
        const int b2 = blockIdx.x - 8192;
        const int kb = (b2 & 31) * 128;   // k tile base (k-values)
        const int nb = (b2 >> 5) * 32;    // n tile base
        const int t = threadIdx.x;
        const int kloc = t >> 5;
        const int nloc = t & 31;
        #pragma unroll
        for (int i = 0; i < 16; i++) {
            int k = kloc + i * 8;
            tsm[nloc][k] = (uint8_t)B[(size_t)(kb + k) * MSZ + nb + nloc];
        }
        __syncthreads();
        // each thread: one n-row, 16 k-values -> 8 packed bytes
        const int n = t >> 3;
        const int k0 = (t & 7) * 16;
        uchar4 w0, w1;
        w0.x = (uint8_t)(tsm[n][k0 + 0] | (tsm[n][k0 + 1] << 4));
        w0.y = (uint8_t)(tsm[n][k0 + 2] | (tsm[n][k0 + 3] << 4));
        w0.z = (uint8_t)(tsm[n][k0 + 4] | (tsm[n][k0 + 5] << 4));
        w0.w = (uint8_t)(tsm[n][k0 + 6] | (tsm[n][k0 + 7] << 4));
        w1.x = (uint8_t)(tsm[n][k0 + 8] | (tsm[n][k0 + 9] << 4));
        w1.y = (uint8_t)(tsm[n][k0 + 10] | (tsm[n][k0 + 11] << 4));
        w1.z = (uint8_t)(tsm[n][k0 + 12] | (tsm[n][k0 + 13] << 4));
        w1.w = (uint8_t)(tsm[n][k0 + 14] | (tsm[n][k0 + 15] << 4));
        uint8_t* dst = &g_packBt[(size_t)(nb + n) * KB2 + (kb + k0) / 2];
        *(uchar4*)dst = w0;
        *(uchar4*)(dst + 4) = w1;
    }
}

// ---------------------------------------------------------------- GEMM
// 128 threads, 4 warps 2(m) x 2(n); warp tile 64x64; CTA 128x128, kt=256 kvals.
__global__ void __launch_bounds__(128, 2)
gemm_kernel(const int* __restrict__ gIn, float* __restrict__ gOut) {
    extern __shared__ uint8_t dsm[];
    const uint32_t smbase = smem_u32(dsm);

    const int tid = threadIdx.x;
    const int l = tid & 31;
    const int warp = tid >> 5;
    const int wm = warp >> 1;
    const int wn = warp & 1;
    const int m0 = blockIdx.y * BM;
    const int n0 = blockIdx.x * BN;

    const int ldRow = tid >> 3;          // 0..15
    const int ldSeg = (tid & 7) * 16;    // 0..112

    // ldmatrix lane-address components. Byte-level layout is identical to the
    // proven s8 path: m16n8k64.u4 quad-lane nibble ranges occupy the same bytes
    // as m16n8k32.s8 quad-lane byte ranges.
    const int aRowL = (l & 7) + ((l >> 3) & 1) * 8;
    const int aChk  = ((l >> 4) & 1) * 16;
    const int bRowL = (l & 7) + ((l >> 4) & 1) * 8;
    const int bChk  = ((l >> 3) & 1) * 16;

    int acc[4][8][4];
    #pragma unroll
    for (int mi = 0; mi < 4; mi++)
        #pragma unroll
        for (int ni = 0; ni < 8; ni++)
            #pragma unroll
            for (int r = 0; r < 4; r++) acc[mi][ni][r] = 0;

    // prologue: 2 stages in flight
    LOAD_STAGE(0, 0);
    LOAD_STAGE(1, 1);

    for (int kt = 0; kt < NKT; kt++) {
        CPW(STAGES - 2);
        __syncthreads();

        if (kt + STAGES - 1 < NKT) { LOAD_STAGE(kt + STAGES - 1, (kt + STAGES - 1) % STAGES); }
        else { CPC(); }

        const uint32_t sA = smbase + (kt % STAGES) * STAGE_BYTES;
        const uint32_t sB = sA + STAGE_A;

        #pragma unroll
        for (int ks = 0; ks < 4; ks++) {   // 4 x 64 k-values = 32 bytes each
            uint32_t a[4][4], b[8][2];
            #pragma unroll
            for (int mi = 0; mi < 4; mi++) {
                uint32_t addr = sA + (uint32_t)(wm * 64 + mi * 16 + aRowL) * ROWB
                              + aChk + ks * 32;
                LDSM4(a[mi][0], a[mi][1], a[mi][2], a[mi][3], addr);
            }
            #pragma unroll
            for (int np = 0; np < 4; np++) {
                uint32_t r0, r1, r2, r3;
                uint32_t addr = sB + (uint32_t)(wn * 64 + np * 16 + bRowL) * ROWB
                              + bChk + ks * 32;
                LDSM4(r0, r1, r2, r3, addr);
                b[np * 2 + 0][0] = r0; b[np * 2 + 0][1] = r1;
                b[np * 2 + 1][0] = r2; b[np * 2 + 1][1] = r3;
            }
            #pragma unroll
            for (int mi = 0; mi < 4; mi++)
                #pragma unroll
                for (int ni = 0; ni < 8; ni++)
                    MMA_U4(acc[mi][ni], a[mi], b[ni]);
        }
    }

    // Epilogue: int add (exact) then f32 convert; float2 stores.
    const int crow = l >> 2;
    const int ccol = (l & 3) * 2;
    #pragma unroll
    for (int mi = 0; mi < 4; mi++) {
        #pragma unroll
        for (int ni = 0; ni < 8; ni++) {
            const int row = m0 + wm * 64 + mi * 16 + crow;
            const int col = n0 + wn * 64 + ni * 8 + ccol;
            const size_t gi = (size_t)row * MSZ + col;
            const int2 in0 = *(const int2*)&gIn[gi];
            const int2 in1 = *(const int2*)&gIn[gi + (size_t)8 * MSZ];
            float2 o0, o1;
            o0.x = (float)(acc[mi][ni][0] + in0.x);
            o0.y = (float)(acc[mi][ni][1] + in0.y);
            o1.x = (float)(acc[mi][ni][2] + in1.x);
            o1.y = (float)(acc[mi][ni][3] + in1.y);
            *(float2*)&gOut[gi] = o0;
            *(float2*)&gOut[gi + (size_t)8 * MSZ] = o1;
        }
    }
}

// ---------------------------------------------------------------- launch
extern "C" void kernel_launch(void* const* d_in, const int* in_sizes, int n_in,
                              void* d_out, int out_size) {
    const int* inp  = (const int*)d_in[0];   // input_tensor [M,N]
    const int* mat1 = (const int*)d_in[1];   // [M,K]
    const int* mat2 = (const int*)d_in[2];   // [K,N]
    float* out = (float*)d_out;

    pack_kernel<<<8192 + 4096, 256>>>(mat1, mat2);

    static int smem_set = 0;
    if (!smem_set) {
        cudaFuncSetAttribute(gemm_kernel, cudaFuncAttributeMaxDynamicSharedMemorySize, SMEM_DYN);
        smem_set = 1;
    }
    gemm_kernel<<<dim3(MSZ / BN, MSZ / BM), 128, SMEM_DYN>>>(inp, out);
}

// round 11
// speedup vs baseline: 3.3690x; 3.3690x over previous
#include <cuda_runtime.h>
#include <cstdint>

// ============================================================================
// out[f32,4096x4096] = mat1[i32] @ mat2[i32] + input[i32], values in [0,16)
// s8 IMMA path (u4 proved ALU-emulated on sm_100 in R10 -> reverted).
// R11: 256 thr, 8 warps (2m x 4n) of 64x32 (64 acc regs -> <=128 regs/thread),
// CTA 128x128x128, 3 stages, 2 CTAs/SM = 16 warps/SM (4/SMSP) for latency hiding.
// ============================================================================

#define MSZ 4096
#define BM 128
#define BN 128
#define BK 128
#define STAGES 3
#define NKT (MSZ / BK)             // 32
#define ROWB 144                   // padded SMEM row: 128 data + 16 pad
#define STAGE_A (BM * ROWB)        // 18432
#define STAGE_B (BN * ROWB)        // 18432
#define STAGE_BYTES (STAGE_A + STAGE_B)      // 36864
#define SMEM_DYN (STAGES * STAGE_BYTES)      // 110592 -> 2 CTAs/SM

// Scratch (device globals; no allocation anywhere)
__device__ __align__(128) uint8_t g_packA[(size_t)MSZ * MSZ];   // [M,K] s8
__device__ __align__(128) uint8_t g_packBt[(size_t)MSZ * MSZ];  // [N,K] s8 (B^T)

// ---------------------------------------------------------------- helpers
__device__ __forceinline__ uint32_t smem_u32(const void* p) {
    uint32_t a;
    asm("{ .reg .u64 t; cvta.to.shared.u64 t, %1; cvt.u32.u64 %0, t; }"
        : "=r"(a) : "l"(p));
    return a;
}

#define CPA16(dst, src) \
    asm volatile("cp.async.cg.shared.global [%0], [%1], 16;" :: "r"(dst), "l"(src) : "memory")
#define CPC() asm volatile("cp.async.commit_group;" ::: "memory")
#define CPW(n) asm volatile("cp.async.wait_group %0;" :: "n"(n) : "memory")

#define LDSM4(r0, r1, r2, r3, addr) \
    asm volatile("ldmatrix.sync.aligned.m8n8.x4.shared.b16 {%0,%1,%2,%3}, [%4];" \
                 : "=r"(r0), "=r"(r1), "=r"(r2), "=r"(r3) : "r"(addr))

#define MMA_S8(d, a, b) \
    asm volatile("mma.sync.aligned.m16n8k32.row.col.s32.s8.s8.s32 " \
                 "{%0,%1,%2,%3}, {%4,%5,%6,%7}, {%8,%9}, {%0,%1,%2,%3};" \
                 : "+r"((d)[0]), "+r"((d)[1]), "+r"((d)[2]), "+r"((d)[3]) \
                 : "r"((a)[0]), "r"((a)[1]), "r"((a)[2]), "r"((a)[3]), \
                   "r"((b)[0]), "r"((b)[1]))

// stage loader: 256 threads; A 1024 + B 1024 16B chunks; 8 per thread.
#define LOAD_STAGE(kt, st) do {                                                           \
    const uint32_t sA_ = smbase + (st) * STAGE_BYTES;                                     \
    const uint32_t sB_ = sA_ + STAGE_A;                                                   \
    const uint8_t* pA_ = g_packA  + (size_t)m0 * MSZ + (size_t)(kt) * BK;                 \
    const uint8_t* pB_ = g_packBt + (size_t)n0 * MSZ + (size_t)(kt) * BK;                 \
    _Pragma("unroll")                                                                     \
    for (int i_ = 0; i_ < 4; i_++) {                                                      \
        const int row_ = ldRow + i_ * 32;                                                 \
        CPA16(sA_ + row_ * ROWB + ldSeg, pA_ + (size_t)row_ * MSZ + ldSeg);               \
        CPA16(sB_ + row_ * ROWB + ldSeg, pB_ + (size_t)row_ * MSZ + ldSeg);               \
    }                                                                                     \
    CPC();                                                                                \
} while (0)

// ---------------------------------------------------------------- fused pack
// blocks [0, 16384): packA; blocks [16384, 20480): packBt 128(k) x 32(n) tiles.
__global__ void pack_kernel(const int* __restrict__ A, const int* __restrict__ B) {
    if (blockIdx.x < 16384) {
        size_t i = (size_t)blockIdx.x * 256 + threadIdx.x;
        int4 v = ((const int4*)A)[i];
        uchar4 r;
        r.x = (uint8_t)v.x; r.y = (uint8_t)v.y; r.z = (uint8_t)v.z; r.w = (uint8_t)v.w;
        ((uchar4*)g_packA)[i] = r;
    } else {
        __shared__ uint8_t tsm[32][132];
        const int b2 = blockIdx.x - 16384;
        const int kb = (b2 & 31) * 128;
        const int nb = (b2 >> 5) * 32;
        const int t = threadIdx.x;
        const int kloc = t >> 5;
        const int nloc = t & 31;
        #pragma unroll
        for (int i = 0; i < 16; i++) {
            int k = kloc + i * 8;
            tsm[nloc][k] = (uint8_t)B[(size_t)(kb + k) * MSZ + nb + nloc];
        }
        __syncthreads();
        const int k4 = (t & 31) * 4;
        const int nrow = t >> 5;
        #pragma unroll
        for (int i = 0; i < 4; i++) {
            int n = nrow + i * 8;
            uchar4 v;
            v.x = tsm[n][k4]; v.y = tsm[n][k4 + 1]; v.z = tsm[n][k4 + 2]; v.w = tsm[n][k4 + 3];
            *(uchar4*)&g_packBt[(size_t)(nb + n) * MSZ + kb + k4] = v;
        }
    }
}

// ---------------------------------------------------------------- GEMM
// 256 threads, 8 warps 2(m) x 4(n); warp tile 64x32; CTA 128x128x128.
__global__ void __launch_bounds__(256, 2)
gemm_kernel(const int* __restrict__ gIn, float* __restrict__ gOut) {
    extern __shared__ uint8_t dsm[];
    const uint32_t smbase = smem_u32(dsm);

    const int tid = threadIdx.x;
    const int l = tid & 31;
    const int warp = tid >> 5;
    const int wm = warp >> 2;        // 0..1
    const int wn = warp & 3;         // 0..3
    const int m0 = blockIdx.y * BM;
    const int n0 = blockIdx.x * BN;

    const int ldRow = tid >> 3;          // 0..31
    const int ldSeg = (tid & 7) * 16;    // 0..112

    // ldmatrix lane-address components (m16n8k32 fragment layout)
    const int aRowL = (l & 7) + ((l >> 3) & 1) * 8;
    const int aChk  = ((l >> 4) & 1) * 16;
    const int bRowL = (l & 7) + ((l >> 4) & 1) * 8;
    const int bChk  = ((l >> 3) & 1) * 16;

    int acc[4][4][4];
    #pragma unroll
    for (int mi = 0; mi < 4; mi++)
        #pragma unroll
        for (int ni = 0; ni < 4; ni++)
            #pragma unroll
            for (int r = 0; r < 4; r++) acc[mi][ni][r] = 0;

    // prologue: 2 stages in flight
    LOAD_STAGE(0, 0);
    LOAD_STAGE(1, 1);

    for (int kt = 0; kt < NKT; kt++) {
        CPW(STAGES - 2);
        __syncthreads();

        if (kt + STAGES - 1 < NKT) { LOAD_STAGE(kt + STAGES - 1, (kt + STAGES - 1) % STAGES); }
        else { CPC(); }

        const uint32_t sA = smbase + (kt % STAGES) * STAGE_BYTES;
        const uint32_t sB = sA + STAGE_A;

        #pragma unroll
        for (int ks = 0; ks < 4; ks++) {
            uint32_t a[4][4], b[4][2];
            #pragma unroll
            for (int mi = 0; mi < 4; mi++) {
                uint32_t addr = sA + (uint32_t)(wm * 64 + mi * 16 + aRowL) * ROWB
                              + aChk + ks * 32;
                LDSM4(a[mi][0], a[mi][1], a[mi][2], a[mi][3], addr);
            }
            #pragma unroll
            for (int np = 0; np < 2; np++) {
                uint32_t r0, r1, r2, r3;
                uint32_t addr = sB + (uint32_t)(wn * 32 + np * 16 + bRowL) * ROWB
                              + bChk + ks * 32;
                LDSM4(r0, r1, r2, r3, addr);
                b[np * 2 + 0][0] = r0; b[np * 2 + 0][1] = r1;
                b[np * 2 + 1][0] = r2; b[np * 2 + 1][1] = r3;
            }
            #pragma unroll
            for (int mi = 0; mi < 4; mi++)
                #pragma unroll
                for (int ni = 0; ni < 4; ni++)
                    MMA_S8(acc[mi][ni], a[mi], b[ni]);
        }
    }

    // Epilogue: int add (exact) then f32 convert; float2 stores.
    const int crow = l >> 2;
    const int ccol = (l & 3) * 2;
    #pragma unroll
    for (int mi = 0; mi < 4; mi++) {
        #pragma unroll
        for (int ni = 0; ni < 4; ni++) {
            const int row = m0 + wm * 64 + mi * 16 + crow;
            const int col = n0 + wn * 32 + ni * 8 + ccol;
            const size_t gi = (size_t)row * MSZ + col;
            const int2 in0 = *(const int2*)&gIn[gi];
            const int2 in1 = *(const int2*)&gIn[gi + (size_t)8 * MSZ];
            float2 o0, o1;
            o0.x = (float)(acc[mi][ni][0] + in0.x);
            o0.y = (float)(acc[mi][ni][1] + in0.y);
            o1.x = (float)(acc[mi][ni][2] + in1.x);
            o1.y = (float)(acc[mi][ni][3] + in1.y);
            *(float2*)&gOut[gi] = o0;
            *(float2*)&gOut[gi + (size_t)8 * MSZ] = o1;
        }
    }
}

// ---------------------------------------------------------------- launch
extern "C" void kernel_launch(void* const* d_in, const int* in_sizes, int n_in,
                              void* d_out, int out_size) {
    const int* inp  = (const int*)d_in[0];   // input_tensor [M,N]
    const int* mat1 = (const int*)d_in[1];   // [M,K]
    const int* mat2 = (const int*)d_in[2];   // [K,N]
    float* out = (float*)d_out;

    pack_kernel<<<16384 + 4096, 256>>>(mat1, mat2);

    static int smem_set = 0;
    if (!smem_set) {
        cudaFuncSetAttribute(gemm_kernel, cudaFuncAttributeMaxDynamicSharedMemorySize, SMEM_DYN);
        smem_set = 1;
    }
    gemm_kernel<<<dim3(MSZ / BN, MSZ / BM), 256, SMEM_DYN>>>(inp, out);
}